// round 8
// baseline (speedup 1.0000x reference)
#include <cuda_runtime.h>
#include <cuda_fp16.h>
#include <math.h>
#include <stdint.h>

// ---------------------------------------------------------------- constants
#define NROWS 32768          // B*L
#define EQ    1280
#define KDIM  1280
#define VQ    32
#define PQ    496
#define N2P   640            // padded width of second GEMM (528 -> 640)
#define LN_EPS 1e-12f
#define KC    32             // K per chunk
#define NCH   (KDIM / KC)    // 40
#define NSTG  3              // cp.async pipeline stages
#define ALO_OFF ((size_t)NROWS * KDIM)   // offset of A-lo within paired buffer

// ---------------------------------------------------------------- scratch
__device__ float g_h[(size_t)NROWS * EQ];            // post-GELU hidden (fp32)
__device__ float g_l2[(size_t)NROWS * N2P];          // [pi_logits | Theta | pad]
__device__ __half g_x2[2 * ALO_OFF];                 // hx  (hi | lo) fp16
__device__ __half g_a2[2 * ALO_OFF];                 // LN(h) (hi | lo) fp16
__device__ __half g_w1f[(size_t)EQ * KDIM];          // dense_w^T fp16 [n][k]
__device__ __half g_w2f[(size_t)N2P * KDIM];         // packed [theta|Theta]^T fp16
__device__ float g_b2[N2P];

// ---------------------------------------------------------------- PTX utils
__device__ __forceinline__ uint32_t smem_u32(const void* p) {
    uint32_t a;
    asm("{ .reg .u64 t; cvta.to.shared.u64 t, %1; cvt.u32.u64 %0, t; }"
        : "=r"(a) : "l"(p));
    return a;
}
__device__ __forceinline__ void ldsm4(uint32_t* r, uint32_t addr) {
    asm volatile("ldmatrix.sync.aligned.m8n8.x4.shared.b16 {%0,%1,%2,%3}, [%4];"
                 : "=r"(r[0]), "=r"(r[1]), "=r"(r[2]), "=r"(r[3]) : "r"(addr));
}
__device__ __forceinline__ void mma16816(float* d, const uint32_t* a,
                                         const uint32_t* b) {
    asm volatile(
        "mma.sync.aligned.m16n8k16.row.col.f32.f16.f16.f32 "
        "{%0,%1,%2,%3}, {%4,%5,%6,%7}, {%8,%9}, {%0,%1,%2,%3};"
        : "+f"(d[0]), "+f"(d[1]), "+f"(d[2]), "+f"(d[3])
        : "r"(a[0]), "r"(a[1]), "r"(a[2]), "r"(a[3]), "r"(b[0]), "r"(b[1]));
}
__device__ __forceinline__ void cpasync16(uint32_t dst, const void* src) {
    asm volatile("cp.async.cg.shared.global [%0], [%1], 16;"
                 :: "r"(dst), "l"(src));
}
#define CP_COMMIT() asm volatile("cp.async.commit_group;" ::: "memory")
#define CP_WAIT1()  asm volatile("cp.async.wait_group 1;" ::: "memory")
#define CP_WAIT0()  asm volatile("cp.async.wait_group 0;" ::: "memory")

// fp16 hi/lo split: hi = RN(v), lo = RN(v - hi)
__device__ __forceinline__ void split2h(float v, __half& h, __half& l) {
    h = __float2half_rn(v);
    l = __float2half_rn(v - __half2float(h));
}

// ---------------------------------------------------------------- prep kernels
__global__ void split_x_kernel(const float* __restrict__ x) {
    size_t idx = (size_t)blockIdx.x * blockDim.x + threadIdx.x;
    if (idx >= ALO_OFF / 4) return;
    float4 v = ((const float4*)x)[idx];
    __half h0, h1, h2, h3, l0, l1, l2, l3;
    split2h(v.x, h0, l0); split2h(v.y, h1, l1);
    split2h(v.z, h2, l2); split2h(v.w, h3, l3);
    ushort4 hv = make_ushort4(__half_as_ushort(h0), __half_as_ushort(h1),
                              __half_as_ushort(h2), __half_as_ushort(h3));
    ushort4 lv = make_ushort4(__half_as_ushort(l0), __half_as_ushort(l1),
                              __half_as_ushort(l2), __half_as_ushort(l3));
    ((ushort4*)g_x2)[idx] = hv;
    ((ushort4*)(g_x2 + ALO_OFF))[idx] = lv;
}

__global__ void conv_w1_kernel(const float* __restrict__ w) {
    int idx = blockIdx.x * blockDim.x + threadIdx.x;
    if (idx >= EQ * KDIM) return;
    int n = idx / KDIM;
    int k = idx - n * KDIM;
    g_w1f[idx] = __float2half_rn(w[(size_t)k * EQ + n]);
}

__global__ void conv_w2_kernel(const float* __restrict__ tw,
                               const float* __restrict__ tb,
                               const float* __restrict__ Tw,
                               const float* __restrict__ Tb) {
    int idx = blockIdx.x * blockDim.x + threadIdx.x;
    if (idx < N2P * KDIM) {
        int n = idx / KDIM;
        int k = idx - n * KDIM;
        float v = 0.0f;
        if (n < VQ)           v = tw[(size_t)k * VQ + n];
        else if (n < VQ + PQ) v = Tw[(size_t)k * PQ + (n - VQ)];
        g_w2f[idx] = __float2half_rn(v);
    }
    if (idx < N2P)
        g_b2[idx] = (idx < VQ) ? tb[idx] : (idx < VQ + PQ ? Tb[idx - VQ] : 0.0f);
}

// ---------------------------------------------------------------- GEMM (HMMA)
// C[128x128] = (Ah+Al) @ Bh^T  (fp16 2-pass: hh + lh), K-major.
// 3-stage cp.async pipeline, KC=32, ONE __syncthreads per chunk, 2 CTAs/SM.
// SMEM per stage: 3 pieces (Ah, Al, Bh), each 128 rows x 64B, stride 80B.
template <bool GELU>
__global__ void __launch_bounds__(256, 2)
gemm_mma_kernel(const __half* __restrict__ A2,   // hi at 0, lo at +ALO_OFF
                const __half* __restrict__ Bf,
                const float* __restrict__ bias, float* __restrict__ C,
                int ldc) {
    extern __shared__ char sm[];
    const uint32_t sb = smem_u32(sm);
    constexpr uint32_t RS = 80;
    constexpr uint32_t PIECE = 128 * RS;   // 10240
    constexpr uint32_t STAGE = 3 * PIECE;  // 30720

    int tid = threadIdx.x;
    int lane = tid & 31;
    int wid = tid >> 5;
    int wm = (wid & 3) * 32;
    int wn = (wid >> 2) * 64;
    int m0 = blockIdx.y * 128;
    int n0 = blockIdx.x * 128;

    // cp.async mapping: thread -> (row = tid>>1, one of two 16B chunks)
    int lr = tid >> 1;
    int c16 = (tid & 1) * 2;
    const __half* pAh = A2 + (size_t)(m0 + lr) * KDIM + c16 * 8;
    const __half* pAl = pAh + ALO_OFF;
    const __half* pB  = Bf + (size_t)(n0 + lr) * KDIM + c16 * 8;
    uint32_t sOff = (uint32_t)lr * RS + (uint32_t)c16 * 16;

    auto issue = [&](int c) {
        int buf = c % NSTG;
        uint32_t d = sb + (uint32_t)buf * STAGE + sOff;
        size_t g = (size_t)c * KC;
        cpasync16(d,                  pAh + g);
        cpasync16(d + 16,             pAh + g + 8);
        cpasync16(d + PIECE,          pAl + g);
        cpasync16(d + PIECE + 16,     pAl + g + 8);
        cpasync16(d + 2 * PIECE,      pB + g);
        cpasync16(d + 2 * PIECE + 16, pB + g + 8);
        CP_COMMIT();
    };

    // ldmatrix per-lane offsets
    int rA = (lane & 7) + ((lane >> 3) & 1) * 8;
    uint32_t kA = (uint32_t)((lane >> 4) & 1) * 16;
    int rB = (lane & 7) + ((lane >> 4) & 1) * 8;
    uint32_t kB = (uint32_t)((lane >> 3) & 1) * 16;

    float acc[2][8][4];
#pragma unroll
    for (int i = 0; i < 2; i++)
#pragma unroll
        for (int j = 0; j < 8; j++)
#pragma unroll
            for (int q = 0; q < 4; q++) acc[i][j][q] = 0.0f;

    issue(0);
    issue(1);

    int ksX = wid & 1;   // warp-parity stagger of ks order
    for (int c = 0; c < NCH; c++) {
        // chunk c data ready: with 2 groups outstanding wait_group 1 retires
        // group c; on the final chunk only group NCH-1 is outstanding.
        if (c + 1 < NCH) CP_WAIT1(); else CP_WAIT0();
        // One barrier: publishes chunk c to all warps AND retires all readers
        // of buffer (c+2)%NSTG (its last readers ran in chunk c-1).
        __syncthreads();
        if (c + 2 < NCH) issue(c + 2);

        uint32_t st = sb + (uint32_t)(c % NSTG) * STAGE;
#pragma unroll
        for (int ksi = 0; ksi < 2; ksi++) {
            uint32_t kbyte = (uint32_t)(ksi ^ ksX) * 32;
            uint32_t ah[2][4], al[2][4], bh[8][2];
#pragma unroll
            for (int mf = 0; mf < 2; mf++) {
                uint32_t ad =
                    st + (uint32_t)(wm + mf * 16 + rA) * RS + kbyte + kA;
                ldsm4(ah[mf], ad);
                ldsm4(al[mf], ad + PIECE);
            }
#pragma unroll
            for (int g = 0; g < 4; g++) {
                uint32_t t[4];
                ldsm4(t, st + 2 * PIECE +
                             (uint32_t)(wn + g * 16 + rB) * RS + kbyte + kB);
                bh[2 * g][0] = t[0]; bh[2 * g][1] = t[1];
                bh[2 * g + 1][0] = t[2]; bh[2 * g + 1][1] = t[3];
            }
            // pass hh (16 independent accumulators)
#pragma unroll
            for (int mf = 0; mf < 2; mf++)
#pragma unroll
                for (int nf = 0; nf < 8; nf++)
                    mma16816(acc[mf][nf], ah[mf], bh[nf]);
            // pass lh
#pragma unroll
            for (int mf = 0; mf < 2; mf++)
#pragma unroll
                for (int nf = 0; nf < 8; nf++)
                    mma16816(acc[mf][nf], al[mf], bh[nf]);
        }
    }

    // epilogue: bias (+ GELU), direct global stores
    int tr = lane >> 2;
    int tc = (lane & 3) * 2;
#pragma unroll
    for (int mf = 0; mf < 2; mf++) {
#pragma unroll
        for (int nf = 0; nf < 8; nf++) {
            int col = n0 + wn + nf * 8 + tc;
            float2 bb = *(const float2*)&bias[col];
            int r1 = m0 + wm + mf * 16 + tr;
#pragma unroll
            for (int h = 0; h < 2; h++) {
                float v0 = acc[mf][nf][2 * h + 0] + bb.x;
                float v1 = acc[mf][nf][2 * h + 1] + bb.y;
                if (GELU) {
                    v0 = 0.5f * v0 * (1.0f + erff(v0 * 0.70710678118654752f));
                    v1 = 0.5f * v1 * (1.0f + erff(v1 * 0.70710678118654752f));
                }
                *(float2*)&C[(size_t)(r1 + 8 * h) * ldc + col] =
                    make_float2(v0, v1);
            }
        }
    }
}

// ---------------------------------------------------------------- LayerNorm
__device__ __forceinline__ float block_reduce_sum(float v) {
    __shared__ float sh[8];
#pragma unroll
    for (int o = 16; o > 0; o >>= 1) v += __shfl_xor_sync(0xffffffffu, v, o);
    int lane = threadIdx.x & 31, wid = threadIdx.x >> 5;
    if (lane == 0) sh[wid] = v;
    __syncthreads();
    v = (lane < 8) ? sh[lane] : 0.0f;
#pragma unroll
    for (int o = 4; o > 0; o >>= 1) v += __shfl_xor_sync(0xffffffffu, v, o);
    v = __shfl_sync(0xffffffffu, v, 0);
    __syncthreads();
    return v;
}

// LN reads fp32 h, writes normalized output pre-split into fp16 hi/lo.
__global__ void ln_kernel(const float* __restrict__ h,
                          const float* __restrict__ g,
                          const float* __restrict__ b) {
    size_t r = blockIdx.x;
    const float* row = h + r * EQ;
    int t = threadIdx.x;
    float x[5];
    float s = 0.0f;
#pragma unroll
    for (int i = 0; i < 5; i++) { x[i] = row[t + i * 256]; s += x[i]; }
    float mu = block_reduce_sum(s) * (1.0f / EQ);
    float v = 0.0f;
#pragma unroll
    for (int i = 0; i < 5; i++) { float d = x[i] - mu; v += d * d; }
    float var = block_reduce_sum(v) * (1.0f / EQ);
    float inv = rsqrtf(var + LN_EPS);
#pragma unroll
    for (int i = 0; i < 5; i++) {
        int c = t + i * 256;
        float y = (x[i] - mu) * inv * g[c] + b[c];
        __half hh, ll;
        split2h(y, hh, ll);
        g_a2[r * EQ + c] = hh;
        g_a2[ALO_OFF + r * EQ + c] = ll;
    }
}

// ---------------------------------------------------------------- finalize
__global__ void __launch_bounds__(256)
finalize_kernel(const int* __restrict__ mask32,
                float* __restrict__ qOut, float* __restrict__ piOut) {
    __shared__ float th[8][512];
    __shared__ float psq[8][32];
    __shared__ float mf[32];

    int lane = threadIdx.x;
    int w = threadIdx.y;
    size_t r = (size_t)blockIdx.x * 8 + w;

    if (w == 0) mf[lane] = (mask32[lane] != 0) ? 1.0f : 0.0f;
    __syncthreads();

    const float* base = g_l2 + r * N2P;

    bool mk = mf[lane] > 0.5f;
    float x = base[lane];
    float xm = mk ? x : -INFINITY;
    float mx = xm;
#pragma unroll
    for (int o = 16; o > 0; o >>= 1)
        mx = fmaxf(mx, __shfl_xor_sync(0xffffffffu, mx, o));
    float e = mk ? expf(xm - mx) : 0.0f;
    float ssum = e;
#pragma unroll
    for (int o = 16; o > 0; o >>= 1)
        ssum += __shfl_xor_sync(0xffffffffu, ssum, o);

    if (piOut) piOut[r * VQ + lane] = e / ssum;
    float logpi = xm - mx - logf(ssum);
    psq[w][lane] = mk ? expf(0.5f * logpi) : 1.0f;

    for (int idx = lane; idx < PQ; idx += 32) {
        float t = base[VQ + idx];
        th[w][idx] = fmaxf(t, 0.0f) + log1pf(expf(-fabsf(t)));
    }
    __syncwarp();

    int i = lane;
    float mi = mf[i];
    float inv = 1.0f / psq[w][i];
    float q[32];
    float rs = 0.0f;
#pragma unroll
    for (int j = 0; j < 32; j++) {
        float val = 0.0f;
        if (j != i) {
            int lo = min(i, j), hi = max(i, j);
            int idx = lo * VQ - (lo * (lo + 1)) / 2 + (hi - lo - 1);
            val = th[w][idx] * mi * mf[j] * psq[w][j] * inv;
        }
        q[j] = val;
        rs += val;
    }
#pragma unroll
    for (int j = 0; j < 32; j++)
        if (j == i) q[j] = -rs;

    float* out = qOut + r * (VQ * VQ) + (size_t)i * VQ;
#pragma unroll
    for (int j = 0; j < 32; j += 4)
        *(float4*)(out + j) = make_float4(q[j], q[j + 1], q[j + 2], q[j + 3]);
}

// ---------------------------------------------------------------- launch
extern "C" void kernel_launch(void* const* d_in, const int* in_sizes, int n_in,
                              void* d_out, int out_size) {
    const float* hx      = (const float*)d_in[0];
    const int*   vmask   = (const int*)d_in[1];
    const float* dense_w = (const float*)d_in[2];
    const float* dense_b = (const float*)d_in[3];
    const float* ln_g    = (const float*)d_in[4];
    const float* ln_b    = (const float*)d_in[5];
    const float* theta_w = (const float*)d_in[6];
    const float* theta_b = (const float*)d_in[7];
    const float* Theta_w = (const float*)d_in[8];
    const float* Theta_b = (const float*)d_in[9];

    float *hptr, *l2ptr, *b2ptr;
    __half *x2, *a2, *w1f, *w2f;
    cudaGetSymbolAddress((void**)&hptr, g_h);
    cudaGetSymbolAddress((void**)&l2ptr, g_l2);
    cudaGetSymbolAddress((void**)&b2ptr, g_b2);
    cudaGetSymbolAddress((void**)&x2, g_x2);
    cudaGetSymbolAddress((void**)&a2, g_a2);
    cudaGetSymbolAddress((void**)&w1f, g_w1f);
    cudaGetSymbolAddress((void**)&w2f, g_w2f);

    const size_t Q_ELEMS = (size_t)NROWS * VQ * VQ;
    const size_t PI_ELEMS = (size_t)NROWS * VQ;
    float* qOut = (float*)d_out;
    float* piOut = ((size_t)out_size >= Q_ELEMS + PI_ELEMS) ? (qOut + Q_ELEMS)
                                                            : nullptr;

    const int SMEM = NSTG * 3 * 128 * 80;   // 92160 bytes -> 2 CTAs/SM
    cudaFuncSetAttribute(gemm_mma_kernel<true>,
                         cudaFuncAttributeMaxDynamicSharedMemorySize, SMEM);
    cudaFuncSetAttribute(gemm_mma_kernel<false>,
                         cudaFuncAttributeMaxDynamicSharedMemorySize, SMEM);

    // 1. prep: split activations to fp16 hi/lo; weights to fp16 (K-major)
    split_x_kernel<<<(int)(ALO_OFF / 4 + 255) / 256, 256>>>(hx);
    conv_w1_kernel<<<(EQ * KDIM + 255) / 256, 256>>>(dense_w);
    conv_w2_kernel<<<(N2P * KDIM + 255) / 256, 256>>>(theta_w, theta_b,
                                                      Theta_w, Theta_b);

    // 2. h = gelu(hx @ dense_w + dense_b)   [M=32768, N=1280, K=1280]
    {
        dim3 grid(EQ / 128, NROWS / 128);
        gemm_mma_kernel<true><<<grid, 256, SMEM>>>(x2, w1f, dense_b, hptr, EQ);
    }

    // 3. LayerNorm (writes fp16 hi/lo split)
    ln_kernel<<<NROWS, 256>>>(hptr, ln_g, ln_b);

    // 4. logits2 = LN(h) @ [theta|Theta] + bias  [M=32768, N=640, K=1280]
    {
        dim3 grid(N2P / 128, NROWS / 128);
        gemm_mma_kernel<false><<<grid, 256, SMEM>>>(a2, w2f, b2ptr, l2ptr, N2P);
    }

    // 5. per-row epilogue -> Q, pi
    finalize_kernel<<<NROWS / 8, dim3(32, 8)>>>(vmask, qOut, piOut);
}

// round 9
// speedup vs baseline: 1.4546x; 1.4546x over previous
#include <cuda_runtime.h>
#include <cuda_fp16.h>
#include <math.h>
#include <stdint.h>

// ---------------------------------------------------------------- constants
#define NROWS 32768          // B*L
#define EQ    1280
#define KDIM  1280
#define VQ    32
#define PQ    496
#define N2P   640            // padded width of second GEMM (528 -> 640)
#define LN_EPS 1e-12f
#define KC    32             // K per chunk
#define NCH   (KDIM / KC)    // 40
#define NSTG  4              // cp.async pipeline stages

// ---------------------------------------------------------------- scratch
__device__ float g_h[(size_t)NROWS * EQ];            // post-GELU hidden (fp32)
__device__ float g_l2[(size_t)NROWS * N2P];          // [pi_logits | Theta | pad]
__device__ __half g_xf[(size_t)NROWS * KDIM];        // hx fp16
__device__ __half g_af[(size_t)NROWS * KDIM];        // LN(h) fp16
__device__ __half g_w1f[(size_t)EQ * KDIM];          // dense_w^T fp16 [n][k]
__device__ __half g_w2f[(size_t)N2P * KDIM];         // packed [theta|Theta]^T fp16
__device__ float g_b2[N2P];

// ---------------------------------------------------------------- PTX utils
__device__ __forceinline__ uint32_t smem_u32(const void* p) {
    uint32_t a;
    asm("{ .reg .u64 t; cvta.to.shared.u64 t, %1; cvt.u32.u64 %0, t; }"
        : "=r"(a) : "l"(p));
    return a;
}
__device__ __forceinline__ void ldsm4(uint32_t* r, uint32_t addr) {
    asm volatile("ldmatrix.sync.aligned.m8n8.x4.shared.b16 {%0,%1,%2,%3}, [%4];"
                 : "=r"(r[0]), "=r"(r[1]), "=r"(r[2]), "=r"(r[3]) : "r"(addr));
}
__device__ __forceinline__ void mma16816(float* d, const uint32_t* a,
                                         const uint32_t* b) {
    asm volatile(
        "mma.sync.aligned.m16n8k16.row.col.f32.f16.f16.f32 "
        "{%0,%1,%2,%3}, {%4,%5,%6,%7}, {%8,%9}, {%0,%1,%2,%3};"
        : "+f"(d[0]), "+f"(d[1]), "+f"(d[2]), "+f"(d[3])
        : "r"(a[0]), "r"(a[1]), "r"(a[2]), "r"(a[3]), "r"(b[0]), "r"(b[1]));
}
__device__ __forceinline__ void cpasync16(uint32_t dst, const void* src) {
    asm volatile("cp.async.cg.shared.global [%0], [%1], 16;"
                 :: "r"(dst), "l"(src));
}
#define CP_COMMIT() asm volatile("cp.async.commit_group;" ::: "memory")
#define CP_WAIT2()  asm volatile("cp.async.wait_group 2;" ::: "memory")
#define CP_WAIT0()  asm volatile("cp.async.wait_group 0;" ::: "memory")

// ---------------------------------------------------------------- prep kernels
__global__ void conv_x_kernel(const float* __restrict__ x) {
    size_t idx = (size_t)blockIdx.x * blockDim.x + threadIdx.x;
    if (idx >= (size_t)NROWS * KDIM / 4) return;
    float4 v = ((const float4*)x)[idx];
    ushort4 hv = make_ushort4(__half_as_ushort(__float2half_rn(v.x)),
                              __half_as_ushort(__float2half_rn(v.y)),
                              __half_as_ushort(__float2half_rn(v.z)),
                              __half_as_ushort(__float2half_rn(v.w)));
    ((ushort4*)g_xf)[idx] = hv;
}

__global__ void conv_w1_kernel(const float* __restrict__ w) {
    int idx = blockIdx.x * blockDim.x + threadIdx.x;
    if (idx >= EQ * KDIM) return;
    int n = idx / KDIM;
    int k = idx - n * KDIM;
    g_w1f[idx] = __float2half_rn(w[(size_t)k * EQ + n]);
}

__global__ void conv_w2_kernel(const float* __restrict__ tw,
                               const float* __restrict__ tb,
                               const float* __restrict__ Tw,
                               const float* __restrict__ Tb) {
    int idx = blockIdx.x * blockDim.x + threadIdx.x;
    if (idx < N2P * KDIM) {
        int n = idx / KDIM;
        int k = idx - n * KDIM;
        float v = 0.0f;
        if (n < VQ)           v = tw[(size_t)k * VQ + n];
        else if (n < VQ + PQ) v = Tw[(size_t)k * PQ + (n - VQ)];
        g_w2f[idx] = __float2half_rn(v);
    }
    if (idx < N2P)
        g_b2[idx] = (idx < VQ) ? tb[idx] : (idx < VQ + PQ ? Tb[idx - VQ] : 0.0f);
}

// ---------------------------------------------------------------- GEMM (HMMA)
// C[128x128] = A @ B^T, pure fp16 operands, fp32 accumulate. K-major.
// 4-stage cp.async pipeline, KC=32, one __syncthreads per chunk, 2 CTAs/SM.
// SMEM per stage: 2 pieces (A, B), each 128 rows x 64B, stride 80B.
template <bool GELU>
__global__ void __launch_bounds__(256, 2)
gemm_mma_kernel(const __half* __restrict__ Af,
                const __half* __restrict__ Bf,
                const float* __restrict__ bias, float* __restrict__ C,
                int ldc) {
    extern __shared__ char sm[];
    const uint32_t sb = smem_u32(sm);
    constexpr uint32_t RS = 80;
    constexpr uint32_t PIECE = 128 * RS;   // 10240
    constexpr uint32_t STAGE = 2 * PIECE;  // 20480

    int tid = threadIdx.x;
    int lane = tid & 31;
    int wid = tid >> 5;
    int wm = (wid & 3) * 32;
    int wn = (wid >> 2) * 64;
    int m0 = blockIdx.y * 128;
    int n0 = blockIdx.x * 128;

    // cp.async mapping: thread -> (row = tid>>1, one of two 16B chunks)
    int lr = tid >> 1;
    int c16 = (tid & 1) * 2;
    const __half* pA = Af + (size_t)(m0 + lr) * KDIM + c16 * 8;
    const __half* pB = Bf + (size_t)(n0 + lr) * KDIM + c16 * 8;
    uint32_t sOff = (uint32_t)lr * RS + (uint32_t)c16 * 16;

    auto issue = [&](int c) {
        uint32_t d = sb + (uint32_t)(c & (NSTG - 1)) * STAGE + sOff;
        size_t g = (size_t)c * KC;
        cpasync16(d,              pA + g);
        cpasync16(d + 16,         pA + g + 8);
        cpasync16(d + PIECE,      pB + g);
        cpasync16(d + PIECE + 16, pB + g + 8);
        CP_COMMIT();
    };

    // ldmatrix per-lane offsets
    int rA = (lane & 7) + ((lane >> 3) & 1) * 8;
    uint32_t kA = (uint32_t)((lane >> 4) & 1) * 16;
    int rB = (lane & 7) + ((lane >> 4) & 1) * 8;
    uint32_t kB = (uint32_t)((lane >> 3) & 1) * 16;

    float acc[2][8][4];
#pragma unroll
    for (int i = 0; i < 2; i++)
#pragma unroll
        for (int j = 0; j < 8; j++)
#pragma unroll
            for (int q = 0; q < 4; q++) acc[i][j][q] = 0.0f;

    issue(0);
    issue(1);
    issue(2);

    int ksX = wid & 1;   // warp-parity stagger of ks order
    for (int c = 0; c < NCH; c++) {
        // chunk c landed: 3 groups outstanding -> wait_group 2 retires group c
        if (c + 2 < NCH) CP_WAIT2(); else CP_WAIT0();
        // single barrier: publishes chunk c; retires readers of buf (c+3)%4
        __syncthreads();
        if (c + 3 < NCH) issue(c + 3);

        uint32_t st = sb + (uint32_t)(c & (NSTG - 1)) * STAGE;
#pragma unroll
        for (int ksi = 0; ksi < 2; ksi++) {
            uint32_t kbyte = (uint32_t)(ksi ^ ksX) * 32;
            uint32_t ah[2][4], bh[8][2];
#pragma unroll
            for (int mf = 0; mf < 2; mf++)
                ldsm4(ah[mf],
                      st + (uint32_t)(wm + mf * 16 + rA) * RS + kbyte + kA);
#pragma unroll
            for (int g = 0; g < 4; g++) {
                uint32_t t[4];
                ldsm4(t, st + PIECE +
                             (uint32_t)(wn + g * 16 + rB) * RS + kbyte + kB);
                bh[2 * g][0] = t[0]; bh[2 * g][1] = t[1];
                bh[2 * g + 1][0] = t[2]; bh[2 * g + 1][1] = t[3];
            }
#pragma unroll
            for (int mf = 0; mf < 2; mf++)
#pragma unroll
                for (int nf = 0; nf < 8; nf++)
                    mma16816(acc[mf][nf], ah[mf], bh[nf]);
        }
    }

    // epilogue: bias (+ GELU), direct global stores
    int tr = lane >> 2;
    int tc = (lane & 3) * 2;
#pragma unroll
    for (int mf = 0; mf < 2; mf++) {
#pragma unroll
        for (int nf = 0; nf < 8; nf++) {
            int col = n0 + wn + nf * 8 + tc;
            float2 bb = *(const float2*)&bias[col];
            int r1 = m0 + wm + mf * 16 + tr;
#pragma unroll
            for (int h = 0; h < 2; h++) {
                float v0 = acc[mf][nf][2 * h + 0] + bb.x;
                float v1 = acc[mf][nf][2 * h + 1] + bb.y;
                if (GELU) {
                    v0 = 0.5f * v0 * (1.0f + erff(v0 * 0.70710678118654752f));
                    v1 = 0.5f * v1 * (1.0f + erff(v1 * 0.70710678118654752f));
                }
                *(float2*)&C[(size_t)(r1 + 8 * h) * ldc + col] =
                    make_float2(v0, v1);
            }
        }
    }
}

// ---------------------------------------------------------------- LayerNorm
__device__ __forceinline__ float block_reduce_sum(float v) {
    __shared__ float sh[8];
#pragma unroll
    for (int o = 16; o > 0; o >>= 1) v += __shfl_xor_sync(0xffffffffu, v, o);
    int lane = threadIdx.x & 31, wid = threadIdx.x >> 5;
    if (lane == 0) sh[wid] = v;
    __syncthreads();
    v = (lane < 8) ? sh[lane] : 0.0f;
#pragma unroll
    for (int o = 4; o > 0; o >>= 1) v += __shfl_xor_sync(0xffffffffu, v, o);
    v = __shfl_sync(0xffffffffu, v, 0);
    __syncthreads();
    return v;
}

// LN reads fp32 h, writes normalized output as fp16.
__global__ void ln_kernel(const float* __restrict__ h,
                          const float* __restrict__ g,
                          const float* __restrict__ b) {
    size_t r = blockIdx.x;
    const float* row = h + r * EQ;
    int t = threadIdx.x;
    float x[5];
    float s = 0.0f;
#pragma unroll
    for (int i = 0; i < 5; i++) { x[i] = row[t + i * 256]; s += x[i]; }
    float mu = block_reduce_sum(s) * (1.0f / EQ);
    float v = 0.0f;
#pragma unroll
    for (int i = 0; i < 5; i++) { float d = x[i] - mu; v += d * d; }
    float var = block_reduce_sum(v) * (1.0f / EQ);
    float inv = rsqrtf(var + LN_EPS);
#pragma unroll
    for (int i = 0; i < 5; i++) {
        int c = t + i * 256;
        float y = (x[i] - mu) * inv * g[c] + b[c];
        g_af[r * EQ + c] = __float2half_rn(y);
    }
}

// ---------------------------------------------------------------- finalize
__global__ void __launch_bounds__(256)
finalize_kernel(const int* __restrict__ mask32,
                float* __restrict__ qOut, float* __restrict__ piOut) {
    __shared__ float th[8][512];
    __shared__ float psq[8][32];
    __shared__ float mf[32];

    int lane = threadIdx.x;
    int w = threadIdx.y;
    size_t r = (size_t)blockIdx.x * 8 + w;

    if (w == 0) mf[lane] = (mask32[lane] != 0) ? 1.0f : 0.0f;
    __syncthreads();

    const float* base = g_l2 + r * N2P;

    bool mk = mf[lane] > 0.5f;
    float x = base[lane];
    float xm = mk ? x : -INFINITY;
    float mx = xm;
#pragma unroll
    for (int o = 16; o > 0; o >>= 1)
        mx = fmaxf(mx, __shfl_xor_sync(0xffffffffu, mx, o));
    float e = mk ? expf(xm - mx) : 0.0f;
    float ssum = e;
#pragma unroll
    for (int o = 16; o > 0; o >>= 1)
        ssum += __shfl_xor_sync(0xffffffffu, ssum, o);

    if (piOut) piOut[r * VQ + lane] = e / ssum;
    float logpi = xm - mx - logf(ssum);
    psq[w][lane] = mk ? expf(0.5f * logpi) : 1.0f;

    for (int idx = lane; idx < PQ; idx += 32) {
        float t = base[VQ + idx];
        th[w][idx] = fmaxf(t, 0.0f) + log1pf(expf(-fabsf(t)));
    }
    __syncwarp();

    int i = lane;
    float mi = mf[i];
    float inv = 1.0f / psq[w][i];
    float q[32];
    float rs = 0.0f;
#pragma unroll
    for (int j = 0; j < 32; j++) {
        float val = 0.0f;
        if (j != i) {
            int lo = min(i, j), hi = max(i, j);
            int idx = lo * VQ - (lo * (lo + 1)) / 2 + (hi - lo - 1);
            val = th[w][idx] * mi * mf[j] * psq[w][j] * inv;
        }
        q[j] = val;
        rs += val;
    }
#pragma unroll
    for (int j = 0; j < 32; j++)
        if (j == i) q[j] = -rs;

    float* out = qOut + r * (VQ * VQ) + (size_t)i * VQ;
#pragma unroll
    for (int j = 0; j < 32; j += 4)
        *(float4*)(out + j) = make_float4(q[j], q[j + 1], q[j + 2], q[j + 3]);
}

// ---------------------------------------------------------------- launch
extern "C" void kernel_launch(void* const* d_in, const int* in_sizes, int n_in,
                              void* d_out, int out_size) {
    const float* hx      = (const float*)d_in[0];
    const int*   vmask   = (const int*)d_in[1];
    const float* dense_w = (const float*)d_in[2];
    const float* dense_b = (const float*)d_in[3];
    const float* ln_g    = (const float*)d_in[4];
    const float* ln_b    = (const float*)d_in[5];
    const float* theta_w = (const float*)d_in[6];
    const float* theta_b = (const float*)d_in[7];
    const float* Theta_w = (const float*)d_in[8];
    const float* Theta_b = (const float*)d_in[9];

    float *hptr, *l2ptr, *b2ptr;
    __half *xf, *af, *w1f, *w2f;
    cudaGetSymbolAddress((void**)&hptr, g_h);
    cudaGetSymbolAddress((void**)&l2ptr, g_l2);
    cudaGetSymbolAddress((void**)&b2ptr, g_b2);
    cudaGetSymbolAddress((void**)&xf, g_xf);
    cudaGetSymbolAddress((void**)&af, g_af);
    cudaGetSymbolAddress((void**)&w1f, g_w1f);
    cudaGetSymbolAddress((void**)&w2f, g_w2f);

    const size_t Q_ELEMS = (size_t)NROWS * VQ * VQ;
    const size_t PI_ELEMS = (size_t)NROWS * VQ;
    float* qOut = (float*)d_out;
    float* piOut = ((size_t)out_size >= Q_ELEMS + PI_ELEMS) ? (qOut + Q_ELEMS)
                                                            : nullptr;

    const int SMEM = NSTG * 2 * 128 * 80;   // 81920 bytes -> 2 CTAs/SM
    cudaFuncSetAttribute(gemm_mma_kernel<true>,
                         cudaFuncAttributeMaxDynamicSharedMemorySize, SMEM);
    cudaFuncSetAttribute(gemm_mma_kernel<false>,
                         cudaFuncAttributeMaxDynamicSharedMemorySize, SMEM);

    // 1. prep: convert activations/weights to fp16 (weights K-major)
    conv_x_kernel<<<(NROWS * KDIM / 4 + 255) / 256, 256>>>(hx);
    conv_w1_kernel<<<(EQ * KDIM + 255) / 256, 256>>>(dense_w);
    conv_w2_kernel<<<(N2P * KDIM + 255) / 256, 256>>>(theta_w, theta_b,
                                                      Theta_w, Theta_b);

    // 2. h = gelu(hx @ dense_w + dense_b)   [M=32768, N=1280, K=1280]
    {
        dim3 grid(EQ / 128, NROWS / 128);
        gemm_mma_kernel<true><<<grid, 256, SMEM>>>(xf, w1f, dense_b, hptr, EQ);
    }

    // 3. LayerNorm (writes fp16)
    ln_kernel<<<NROWS, 256>>>(hptr, ln_g, ln_b);

    // 4. logits2 = LN(h) @ [theta|Theta] + bias  [M=32768, N=640, K=1280]
    {
        dim3 grid(N2P / 128, NROWS / 128);
        gemm_mma_kernel<false><<<grid, 256, SMEM>>>(af, w2f, b2ptr, l2ptr, N2P);
    }

    // 5. per-row epilogue -> Q, pi
    finalize_kernel<<<NROWS / 8, dim3(32, 8)>>>(vmask, qOut, piOut);
}

// round 10
// speedup vs baseline: 1.4588x; 1.0028x over previous
#include <cuda_runtime.h>
#include <cuda_fp16.h>
#include <math.h>
#include <stdint.h>

// ---------------------------------------------------------------- constants
#define NROWS 32768          // B*L
#define EQ    1280
#define KDIM  1280
#define VQ    32
#define PQ    496
#define N2P   640            // padded width of second GEMM (528 -> 640)
#define LN_EPS 1e-12f
#define KC    32             // K per chunk
#define NCH   (KDIM / KC)    // 40
#define NSTG  4              // cp.async pipeline stages

// ---------------------------------------------------------------- scratch
__device__ __half g_hf[(size_t)NROWS * EQ];          // post-GELU hidden (fp16)
__device__ float g_l2[(size_t)NROWS * N2P];          // [pi_logits | Theta | pad]
__device__ __half g_xf[(size_t)NROWS * KDIM];        // hx fp16
__device__ __half g_af[(size_t)NROWS * KDIM];        // LN(h) fp16
__device__ __half g_w1f[(size_t)EQ * KDIM];          // dense_w^T fp16 [n][k]
__device__ __half g_w2f[(size_t)N2P * KDIM];         // packed [theta|Theta]^T fp16
__device__ float g_b2[N2P];

// ---------------------------------------------------------------- PTX utils
__device__ __forceinline__ uint32_t smem_u32(const void* p) {
    uint32_t a;
    asm("{ .reg .u64 t; cvta.to.shared.u64 t, %1; cvt.u32.u64 %0, t; }"
        : "=r"(a) : "l"(p));
    return a;
}
__device__ __forceinline__ void ldsm4(uint32_t* r, uint32_t addr) {
    asm volatile("ldmatrix.sync.aligned.m8n8.x4.shared.b16 {%0,%1,%2,%3}, [%4];"
                 : "=r"(r[0]), "=r"(r[1]), "=r"(r[2]), "=r"(r[3]) : "r"(addr));
}
__device__ __forceinline__ void mma16816(float* d, const uint32_t* a,
                                         const uint32_t* b) {
    asm volatile(
        "mma.sync.aligned.m16n8k16.row.col.f32.f16.f16.f32 "
        "{%0,%1,%2,%3}, {%4,%5,%6,%7}, {%8,%9}, {%0,%1,%2,%3};"
        : "+f"(d[0]), "+f"(d[1]), "+f"(d[2]), "+f"(d[3])
        : "r"(a[0]), "r"(a[1]), "r"(a[2]), "r"(a[3]), "r"(b[0]), "r"(b[1]));
}
__device__ __forceinline__ void cpasync16(uint32_t dst, const void* src) {
    asm volatile("cp.async.cg.shared.global [%0], [%1], 16;"
                 :: "r"(dst), "l"(src));
}
#define CP_COMMIT() asm volatile("cp.async.commit_group;" ::: "memory")
#define CP_WAIT2()  asm volatile("cp.async.wait_group 2;" ::: "memory")
#define CP_WAIT1()  asm volatile("cp.async.wait_group 1;" ::: "memory")
#define CP_WAIT0()  asm volatile("cp.async.wait_group 0;" ::: "memory")

// ---------------------------------------------------------------- prep kernels
__global__ void conv_x_kernel(const float* __restrict__ x) {
    size_t idx = (size_t)blockIdx.x * blockDim.x + threadIdx.x;
    if (idx >= (size_t)NROWS * KDIM / 4) return;
    float4 v = ((const float4*)x)[idx];
    ushort4 hv = make_ushort4(__half_as_ushort(__float2half_rn(v.x)),
                              __half_as_ushort(__float2half_rn(v.y)),
                              __half_as_ushort(__float2half_rn(v.z)),
                              __half_as_ushort(__float2half_rn(v.w)));
    ((ushort4*)g_xf)[idx] = hv;
}

__global__ void conv_w1_kernel(const float* __restrict__ w) {
    int idx = blockIdx.x * blockDim.x + threadIdx.x;
    if (idx >= EQ * KDIM) return;
    int n = idx / KDIM;
    int k = idx - n * KDIM;
    g_w1f[idx] = __float2half_rn(w[(size_t)k * EQ + n]);
}

__global__ void conv_w2_kernel(const float* __restrict__ tw,
                               const float* __restrict__ tb,
                               const float* __restrict__ Tw,
                               const float* __restrict__ Tb) {
    int idx = blockIdx.x * blockDim.x + threadIdx.x;
    if (idx < N2P * KDIM) {
        int n = idx / KDIM;
        int k = idx - n * KDIM;
        float v = 0.0f;
        if (n < VQ)           v = tw[(size_t)k * VQ + n];
        else if (n < VQ + PQ) v = Tw[(size_t)k * PQ + (n - VQ)];
        g_w2f[idx] = __float2half_rn(v);
    }
    if (idx < N2P)
        g_b2[idx] = (idx < VQ) ? tb[idx] : (idx < VQ + PQ ? Tb[idx - VQ] : 0.0f);
}

// ---------------------------------------------------------------- GEMM (HMMA)
// C[128x128] = A @ B^T, fp16 operands, fp32 accumulate, K-major.
// 4-stage cp.async pipeline, KC=32, register double-buffered fragments:
// LDSM of the next K-step (and the barrier/wait for the next chunk) are
// hidden under the 16 MMAs of the current K-step. 2 CTAs/SM.
template <bool GELU, typename OutT>
__global__ void __launch_bounds__(256, 2)
gemm_mma_kernel(const __half* __restrict__ Af,
                const __half* __restrict__ Bf,
                const float* __restrict__ bias, OutT* __restrict__ C,
                int ldc) {
    extern __shared__ char sm[];
    const uint32_t sb = smem_u32(sm);
    constexpr uint32_t RS = 80;
    constexpr uint32_t PIECE = 128 * RS;   // 10240
    constexpr uint32_t STAGE = 2 * PIECE;  // 20480

    int tid = threadIdx.x;
    int lane = tid & 31;
    int wid = tid >> 5;
    int wm = (wid & 3) * 32;
    int wn = (wid >> 2) * 64;
    int m0 = blockIdx.y * 128;
    int n0 = blockIdx.x * 128;

    // cp.async mapping
    int lr = tid >> 1;
    int c16 = (tid & 1) * 2;
    const __half* pA = Af + (size_t)(m0 + lr) * KDIM + c16 * 8;
    const __half* pB = Bf + (size_t)(n0 + lr) * KDIM + c16 * 8;
    uint32_t sOff = (uint32_t)lr * RS + (uint32_t)c16 * 16;

    auto issue = [&](int c) {
        uint32_t d = sb + (uint32_t)(c & (NSTG - 1)) * STAGE + sOff;
        size_t g = (size_t)c * KC;
        cpasync16(d,              pA + g);
        cpasync16(d + 16,         pA + g + 8);
        cpasync16(d + PIECE,      pB + g);
        cpasync16(d + PIECE + 16, pB + g + 8);
        CP_COMMIT();
    };

    // ldmatrix per-lane offsets
    int rA = (lane & 7) + ((lane >> 3) & 1) * 8;
    uint32_t kA = (uint32_t)((lane >> 4) & 1) * 16;
    int rB = (lane & 7) + ((lane >> 4) & 1) * 8;
    uint32_t kB = (uint32_t)((lane >> 3) & 1) * 16;

    auto ldfrag = [&](uint32_t st, uint32_t kbyte, uint32_t (*ah)[4],
                      uint32_t (*bh)[2]) {
#pragma unroll
        for (int mf = 0; mf < 2; mf++)
            ldsm4(ah[mf], st + (uint32_t)(wm + mf * 16 + rA) * RS + kbyte + kA);
#pragma unroll
        for (int g = 0; g < 4; g++) {
            uint32_t t[4];
            ldsm4(t,
                  st + PIECE + (uint32_t)(wn + g * 16 + rB) * RS + kbyte + kB);
            bh[2 * g][0] = t[0]; bh[2 * g][1] = t[1];
            bh[2 * g + 1][0] = t[2]; bh[2 * g + 1][1] = t[3];
        }
    };

    float acc[2][8][4];
#pragma unroll
    for (int i = 0; i < 2; i++)
#pragma unroll
        for (int j = 0; j < 8; j++)
#pragma unroll
            for (int q = 0; q < 4; q++) acc[i][j][q] = 0.0f;

    uint32_t a0[2][4], b0[8][2];   // fragment buffer: ks0
    uint32_t a1[2][4], b1[8][2];   // fragment buffer: ks1

    issue(0);
    issue(1);
    issue(2);
    CP_WAIT2();          // chunk 0 landed
    __syncthreads();
    ldfrag(sb, 0, a0, b0);

    for (int c = 0; c < NCH; c++) {
        uint32_t st = sb + (uint32_t)(c & (NSTG - 1)) * STAGE;
        // load ks1 fragments of chunk c
        ldfrag(st, 32, a1, b1);
        // MMA ks0 (covers the LDSM latency above)
#pragma unroll
        for (int mf = 0; mf < 2; mf++)
#pragma unroll
            for (int nf = 0; nf < 8; nf++)
                mma16816(acc[mf][nf], a0[mf], b0[nf]);

        if (c + 1 < NCH) {
            // make chunk c+1 visible; retire readers of buffer (c+3)%4
            if (c + 2 < NCH) CP_WAIT1(); else CP_WAIT0();
            __syncthreads();
            if (c + 3 < NCH) issue(c + 3);
            // preload ks0 fragments of chunk c+1 (covered by MMA ks1 below)
            ldfrag(sb + (uint32_t)((c + 1) & (NSTG - 1)) * STAGE, 0, a0, b0);
        }
        // MMA ks1
#pragma unroll
        for (int mf = 0; mf < 2; mf++)
#pragma unroll
            for (int nf = 0; nf < 8; nf++)
                mma16816(acc[mf][nf], a1[mf], b1[nf]);
    }

    // epilogue: bias (+ GELU); OutT = __half (GEMM1) or float (GEMM2)
    int tr = lane >> 2;
    int tc = (lane & 3) * 2;
#pragma unroll
    for (int mf = 0; mf < 2; mf++) {
#pragma unroll
        for (int nf = 0; nf < 8; nf++) {
            int col = n0 + wn + nf * 8 + tc;
            float2 bb = *(const float2*)&bias[col];
            int r1 = m0 + wm + mf * 16 + tr;
#pragma unroll
            for (int h = 0; h < 2; h++) {
                float v0 = acc[mf][nf][2 * h + 0] + bb.x;
                float v1 = acc[mf][nf][2 * h + 1] + bb.y;
                if (GELU) {
                    v0 = 0.5f * v0 * (1.0f + erff(v0 * 0.70710678118654752f));
                    v1 = 0.5f * v1 * (1.0f + erff(v1 * 0.70710678118654752f));
                }
                if constexpr (sizeof(OutT) == 2) {
                    __half2 hv = __floats2half2_rn(v0, v1);
                    *(__half2*)&C[(size_t)(r1 + 8 * h) * ldc + col] = hv;
                } else {
                    *(float2*)&C[(size_t)(r1 + 8 * h) * ldc + col] =
                        make_float2(v0, v1);
                }
            }
        }
    }
}

// ---------------------------------------------------------------- LayerNorm
__device__ __forceinline__ float block_reduce_sum(float v) {
    __shared__ float sh[8];
#pragma unroll
    for (int o = 16; o > 0; o >>= 1) v += __shfl_xor_sync(0xffffffffu, v, o);
    int lane = threadIdx.x & 31, wid = threadIdx.x >> 5;
    if (lane == 0) sh[wid] = v;
    __syncthreads();
    v = (lane < 8) ? sh[lane] : 0.0f;
#pragma unroll
    for (int o = 4; o > 0; o >>= 1) v += __shfl_xor_sync(0xffffffffu, v, o);
    v = __shfl_sync(0xffffffffu, v, 0);
    __syncthreads();
    return v;
}

// LN reads fp16 h, computes stats in fp32, writes fp16.
__global__ void ln_kernel(const __half* __restrict__ h,
                          const float* __restrict__ g,
                          const float* __restrict__ b) {
    size_t r = blockIdx.x;
    const __half* row = h + r * EQ;
    int t = threadIdx.x;
    float x[5];
    float s = 0.0f;
#pragma unroll
    for (int i = 0; i < 5; i++) {
        x[i] = __half2float(row[t + i * 256]);
        s += x[i];
    }
    float mu = block_reduce_sum(s) * (1.0f / EQ);
    float v = 0.0f;
#pragma unroll
    for (int i = 0; i < 5; i++) { float d = x[i] - mu; v += d * d; }
    float var = block_reduce_sum(v) * (1.0f / EQ);
    float inv = rsqrtf(var + LN_EPS);
#pragma unroll
    for (int i = 0; i < 5; i++) {
        int c = t + i * 256;
        float y = (x[i] - mu) * inv * g[c] + b[c];
        g_af[r * EQ + c] = __float2half_rn(y);
    }
}

// ---------------------------------------------------------------- finalize
__global__ void __launch_bounds__(256)
finalize_kernel(const int* __restrict__ mask32,
                float* __restrict__ qOut, float* __restrict__ piOut) {
    __shared__ float th[8][512];
    __shared__ float psq[8][32];
    __shared__ float mf[32];

    int lane = threadIdx.x;
    int w = threadIdx.y;
    size_t r = (size_t)blockIdx.x * 8 + w;

    if (w == 0) mf[lane] = (mask32[lane] != 0) ? 1.0f : 0.0f;
    __syncthreads();

    const float* base = g_l2 + r * N2P;

    bool mk = mf[lane] > 0.5f;
    float x = base[lane];
    float xm = mk ? x : -INFINITY;
    float mx = xm;
#pragma unroll
    for (int o = 16; o > 0; o >>= 1)
        mx = fmaxf(mx, __shfl_xor_sync(0xffffffffu, mx, o));
    float e = mk ? expf(xm - mx) : 0.0f;
    float ssum = e;
#pragma unroll
    for (int o = 16; o > 0; o >>= 1)
        ssum += __shfl_xor_sync(0xffffffffu, ssum, o);

    if (piOut) piOut[r * VQ + lane] = e / ssum;
    float logpi = xm - mx - logf(ssum);
    psq[w][lane] = mk ? expf(0.5f * logpi) : 1.0f;

    for (int idx = lane; idx < PQ; idx += 32) {
        float t = base[VQ + idx];
        th[w][idx] = fmaxf(t, 0.0f) + log1pf(expf(-fabsf(t)));
    }
    __syncwarp();

    int i = lane;
    float mi = mf[i];
    float inv = 1.0f / psq[w][i];
    float q[32];
    float rs = 0.0f;
#pragma unroll
    for (int j = 0; j < 32; j++) {
        float val = 0.0f;
        if (j != i) {
            int lo = min(i, j), hi = max(i, j);
            int idx = lo * VQ - (lo * (lo + 1)) / 2 + (hi - lo - 1);
            val = th[w][idx] * mi * mf[j] * psq[w][j] * inv;
        }
        q[j] = val;
        rs += val;
    }
#pragma unroll
    for (int j = 0; j < 32; j++)
        if (j == i) q[j] = -rs;

    float* out = qOut + r * (VQ * VQ) + (size_t)i * VQ;
#pragma unroll
    for (int j = 0; j < 32; j += 4)
        *(float4*)(out + j) = make_float4(q[j], q[j + 1], q[j + 2], q[j + 3]);
}

// ---------------------------------------------------------------- launch
extern "C" void kernel_launch(void* const* d_in, const int* in_sizes, int n_in,
                              void* d_out, int out_size) {
    const float* hx      = (const float*)d_in[0];
    const int*   vmask   = (const int*)d_in[1];
    const float* dense_w = (const float*)d_in[2];
    const float* dense_b = (const float*)d_in[3];
    const float* ln_g    = (const float*)d_in[4];
    const float* ln_b    = (const float*)d_in[5];
    const float* theta_w = (const float*)d_in[6];
    const float* theta_b = (const float*)d_in[7];
    const float* Theta_w = (const float*)d_in[8];
    const float* Theta_b = (const float*)d_in[9];

    float *l2ptr, *b2ptr;
    __half *hfp, *xf, *af, *w1f, *w2f;
    cudaGetSymbolAddress((void**)&hfp, g_hf);
    cudaGetSymbolAddress((void**)&l2ptr, g_l2);
    cudaGetSymbolAddress((void**)&b2ptr, g_b2);
    cudaGetSymbolAddress((void**)&xf, g_xf);
    cudaGetSymbolAddress((void**)&af, g_af);
    cudaGetSymbolAddress((void**)&w1f, g_w1f);
    cudaGetSymbolAddress((void**)&w2f, g_w2f);

    const size_t Q_ELEMS = (size_t)NROWS * VQ * VQ;
    const size_t PI_ELEMS = (size_t)NROWS * VQ;
    float* qOut = (float*)d_out;
    float* piOut = ((size_t)out_size >= Q_ELEMS + PI_ELEMS) ? (qOut + Q_ELEMS)
                                                            : nullptr;

    const int SMEM = NSTG * 2 * 128 * 80;   // 81920 bytes -> 2 CTAs/SM
    cudaFuncSetAttribute(gemm_mma_kernel<true, __half>,
                         cudaFuncAttributeMaxDynamicSharedMemorySize, SMEM);
    cudaFuncSetAttribute(gemm_mma_kernel<false, float>,
                         cudaFuncAttributeMaxDynamicSharedMemorySize, SMEM);

    // 1. prep: convert activations/weights to fp16 (weights K-major)
    conv_x_kernel<<<(NROWS * KDIM / 4 + 255) / 256, 256>>>(hx);
    conv_w1_kernel<<<(EQ * KDIM + 255) / 256, 256>>>(dense_w);
    conv_w2_kernel<<<(N2P * KDIM + 255) / 256, 256>>>(theta_w, theta_b,
                                                      Theta_w, Theta_b);

    // 2. h = gelu(hx @ dense_w + dense_b) -> fp16   [M=32768, N=1280, K=1280]
    {
        dim3 grid(EQ / 128, NROWS / 128);
        gemm_mma_kernel<true, __half><<<grid, 256, SMEM>>>(xf, w1f, dense_b,
                                                           hfp, EQ);
    }

    // 3. LayerNorm (fp16 in/out, fp32 stats)
    ln_kernel<<<NROWS, 256>>>(hfp, ln_g, ln_b);

    // 4. logits2 = LN(h) @ [theta|Theta] + bias  [M=32768, N=640, K=1280]
    {
        dim3 grid(N2P / 128, NROWS / 128);
        gemm_mma_kernel<false, float><<<grid, 256, SMEM>>>(af, w2f, b2ptr,
                                                           l2ptr, N2P);
    }

    // 5. per-row epilogue -> Q, pi
    finalize_kernel<<<NROWS / 8, dim3(32, 8)>>>(vmask, qOut, piOut);
}